// round 17
// baseline (speedup 1.0000x reference)
#include <cuda_runtime.h>
#include <math.h>

constexpr int N_OSC  = 2048;
constexpr int N_SAMP = 16384;
constexpr int LAT    = 32;
constexpr int HALF   = N_OSC * LAT;               // 65536

constexpr int OSC_CHUNK  = 32;
constexpr int KENT       = LAT + 2;                // 32 segs + pre(32) + post(33)
constexpr int SAMP_CHUNK = 1024;
constexpr int THREADS    = 256;
constexpr int SPT        = 4;
constexpr int N_OSC_BLK  = N_OSC / OSC_CHUNK;      // 64
constexpr int N_SAMP_BLK = N_SAMP / SAMP_CHUNK;    // 16

// Packed f32x2 ops (sm_10x-only, PTX-only)
#define FMA2(d,a,b,c) asm("fma.rn.f32x2 %0,%1,%2,%3;" : "=l"(d) : "l"(a), "l"(b), "l"(c))
#define ADD2(d,a,b)   asm("add.rn.f32x2 %0,%1,%2;"    : "=l"(d) : "l"(a), "l"(b))
#define MUL2(d,a,b)   asm("mul.rn.f32x2 %0,%1,%2;"    : "=l"(d) : "l"(a), "l"(b))
#define PACK2(d,lo,hi)   asm("mov.b64 %0,{%1,%2};" : "=l"(d) : "f"(lo), "f"(hi))
#define UNPACK2(lo,hi,v) asm("mov.b64 {%0,%1},%2;" : "=f"(lo), "=f"(hi) : "l"(v))

__device__ float    g_scratch[N_OSC_BLK * N_SAMP];   // 4 MB partials
__device__ unsigned g_cnt[N_SAMP_BLK];               // wraps 63->0: replay-safe

// sin(2*pi*r), r in [-0.5,0.5]: degree-9 odd poly (validated R12, err ~3e-5)
constexpr float SA1 =  6.2831008f;
constexpr float SA3 = -41.332240f;
constexpr float SA5 =  81.374886f;
constexpr float SA7 = -74.511488f;
constexpr float SA9 =  32.841421f;
constexpr float MAGIC   = 12582912.0f;               // 1.5 * 2^23
constexpr float TWOPI_F = 6.28318530717958648f;

// -----------------------------------------------------------------------------
// WARP-LEVEL pipe specialization:
//   warps 0-3 -> __sinf loop (MUFU pipe);  warps 4-7 -> packed poly (FMA pipe)
// warp->SMSP is w%4, so EVERY SMSP gets one warp of each type per block:
// per-SMSP pipe mixing is enforced by construction (the failure mode of the
// thread-level [R13/14] and block-level [R15] hybrids).
// Tables stored in CYCLES; mufu warps convert via c1t = 2pi*c1 registers and
// a radians copy of the phase base. Sample split: each warp computes its own
// samples with its own method (both methods individually validated 9.2e-5).
// -----------------------------------------------------------------------------
__global__ __launch_bounds__(THREADS, 4)
void osc_kernel(const float* __restrict__ latent, float* __restrict__ out) {
    __shared__ float4 s_pk[OSC_CHUNK * KENT];  // (v, dv, dac, apadj), cycles 17.4KB
    __shared__ float  s_bc[OSC_CHUNK * KENT];  // phase base, cycles        4.4KB
    __shared__ float  s_br[OSC_CHUNK * KENT];  // phase base, radians       4.4KB
    __shared__ unsigned s_old;

    const int tid  = threadIdx.x;
    const int lane = tid & 31;
    const int warp = tid >> 5;
    const int oscBase = blockIdx.y * OSC_CHUNK;

    // ---- phase 0: |latent| passthrough ----
    if (tid < 32) {
        const int idx = ((blockIdx.y * N_SAMP_BLK + blockIdx.x) * 32 + tid) * 4;
        const int src = (idx < HALF) ? (HALF + idx) : (idx - HALF);
        const float4 v = *reinterpret_cast<const float4*>(&latent[src]);
        *reinterpret_cast<float4*>(&out[N_SAMP + idx]) =
            make_float4(fabsf(v.x), fabsf(v.y), fabsf(v.z), fabsf(v.w));
    }

    // ---- phase 1: fp32 warp-scan prologue, 8 warps x 4 oscillators ----
#pragma unroll
    for (int j = 0; j < OSC_CHUNK / 8; ++j) {
        const int o  = warp * (OSC_CHUNK / 8) + j;
        const int go = oscBase + o;
        const float f  = fabsf(latent[(size_t)(N_OSC + go) * LAT + lane]);
        const float a  = fabsf(latent[(size_t)go * LAT + lane]);
        const float fn = __shfl_down_sync(0xffffffffu, f, 1);
        const float an = __shfl_down_sync(0xffffffffu, a, 1);
        const float df = (lane < 31) ? (fn - f) : 0.0f;
        const float da = (lane < 31) ? (an - a) : 0.0f;
        const float t = (lane < 31) ? 256.0f * (f + fn) : 0.0f;
        float sc = t;
#pragma unroll
        for (int d = 1; d < 32; d <<= 1) {
            const float u = __shfl_up_sync(0xffffffffu, sc, d);
            if (lane >= d) sc += u;
        }
        const float f0 = __shfl_sync(0xffffffffu, f, 0);
        const float C  = fmaf(256.0f, f0, sc - t);        // exclusive prefix C_k
        const float r  = fmaf(-2.0f, rintf(0.5f * C), C); // C mod 2, exact
        const float bc = 0.5f * r;                        // base, cycles
        const float dv = df * (1.0f / 512.0f);
        const float dac = da * (1.0f / 256.0f);
        const float aa  = fmaf(da, -0.0009765625f, a);    // ap - da/1024
        const int e = o * KENT + lane;
        s_pk[e] = make_float4(f, dv, dac, aa);
        s_bc[e] = bc;
        s_br[e] = TWOPI_F * bc;
        if (lane == 0) {                                  // pre entry (k=32)
            s_pk[o * KENT + 32] = make_float4(f, 0.0f, 0.0f, a);
            s_bc[o * KENT + 32] = bc;
            s_br[o * KENT + 32] = TWOPI_F * bc;
        }
        if (lane == 31) {                                 // post entry (k=33)
            s_pk[o * KENT + 33] = make_float4(f, 0.0f, 0.0f, a);
            s_bc[o * KENT + 33] = bc;
            s_br[o * KENT + 33] = TWOPI_F * bc;
        }
    }
    __syncthreads();

    // ---- per-thread sample constants: k and c1[s] (half-index, cycles) ----
    const int i0 = blockIdx.x * SAMP_CHUNK + tid * SPT;
    int k;
    float c1[SPT];
    if (i0 < 256) {
        k = 32;
#pragma unroll
        for (int s = 0; s < SPT; ++s) c1[s] = 0.5f * (float)(i0 + s - 255);
    } else if (i0 >= 16128) {
        k = 33;
#pragma unroll
        for (int s = 0; s < SPT; ++s) c1[s] = 0.5f * (float)(i0 + s - 16127);
    } else {
        k = (i0 - 256) >> 9;
        const int m0 = (i0 - 256) & 511;
#pragma unroll
        for (int s = 0; s < SPT; ++s) c1[s] = 0.5f * (float)(m0 + s + 1);
    }

    float acc[SPT] = {0.f, 0.f, 0.f, 0.f};
    const float4* pk = &s_pk[k];
    const float*  bck = &s_bc[k];
    const float*  brk = &s_br[k];

    if (warp < 4) {
        // ===== MUFU warps (SMSP w%4 = 0..3): lean __sinf loop =====
        float c1t[SPT];
#pragma unroll
        for (int s = 0; s < SPT; ++s) c1t[s] = TWOPI_F * c1[s];
#pragma unroll 4
        for (int o = 0; o < OSC_CHUNK; ++o) {
            const float4 p  = pk[o * KENT];            // (v, dv, dac, apadj)
            const float  br = brk[o * KENT];           // radians base
#pragma unroll
            for (int s = 0; s < SPT; ++s) {
                const float t   = fmaf(c1[s], p.y, p.x);   // cycles slope
                const float Q   = fmaf(c1t[s], t, br);     // radians
                const float sv  = __sinf(Q);
                const float amp = fmaf(c1[s], p.z, p.w);
                acc[s] = fmaf(sv, amp, acc[s]);
            }
        }
    } else {
        // ===== POLY warps (SMSP w%4 = 0..3): packed FFMA2 degree-9 =====
        unsigned long long c1p[SPT], acc2[SPT];
        unsigned long long a1p, a3p, a5p, a7p, a9p, mgp, nmgp, non;
        PACK2(a1p, SA1, SA1);  PACK2(a3p, SA3, SA3);  PACK2(a5p, SA5, SA5);
        PACK2(a7p, SA7, SA7);  PACK2(a9p, SA9, SA9);
        PACK2(mgp, MAGIC, MAGIC);  PACK2(nmgp, -MAGIC, -MAGIC);
        PACK2(non, -1.0f, -1.0f);
#pragma unroll
        for (int s = 0; s < SPT; ++s) { PACK2(c1p[s], c1[s], c1[s]); acc2[s] = 0ull; }

#pragma unroll 2
        for (int o = 0; o < OSC_CHUNK; o += 2) {
            const float4 pe = pk[o * KENT];
            const float4 po = pk[(o + 1) * KENT];
            const float  be = bck[o * KENT];
            const float  bo = bck[(o + 1) * KENT];
            unsigned long long fp2, df2, dc2, aa2, bu2;
            PACK2(fp2, pe.x, po.x);
            PACK2(df2, pe.y, po.y);
            PACK2(dc2, pe.z, po.z);
            PACK2(aa2, pe.w, po.w);
            PACK2(bu2, be, bo);
#pragma unroll
            for (int s = 0; s < SPT; ++s) {
                unsigned long long t, u, tm, ri, r, z, h, sv, amp;
                FMA2(t,  c1p[s], df2, fp2);
                FMA2(u,  c1p[s], t,   bu2);    // phase in cycles
                ADD2(tm, u, mgp);
                ADD2(ri, tm, nmgp);            // rint(u)
                FMA2(r,  ri, non, u);          // r = u - rint(u), exact
                MUL2(z,  r, r);
                FMA2(h,  z, a9p, a7p);
                FMA2(h,  h, z, a5p);
                FMA2(h,  h, z, a3p);
                FMA2(h,  h, z, a1p);
                MUL2(sv, h, r);
                FMA2(amp, c1p[s], dc2, aa2);
                FMA2(acc2[s], sv, amp, acc2[s]);
            }
        }
#pragma unroll
        for (int s = 0; s < SPT; ++s) {
            float lo, hi;
            UNPACK2(lo, hi, acc2[s]);
            acc[s] = lo + hi;
        }
    }

    *reinterpret_cast<float4*>(&g_scratch[blockIdx.y * N_SAMP + i0]) =
        make_float4(acc[0], acc[1], acc[2], acc[3]);

    // ---- phase 3: last block per column reduces (fixed order = deterministic) ----
    __threadfence();
    __syncthreads();
    if (tid == 0)
        s_old = atomicInc(&g_cnt[blockIdx.x], N_OSC_BLK - 1);   // wraps 63 -> 0
    __syncthreads();

    if (s_old == N_OSC_BLK - 1) {
        __threadfence();
        const int j0 = blockIdx.x * SAMP_CHUNK + tid * 4;
        float4 a0 = make_float4(0.f, 0.f, 0.f, 0.f);
        float4 a1 = a0;
#pragma unroll
        for (int b = 0; b < N_OSC_BLK; b += 2) {
            const float4 v0 = *reinterpret_cast<const float4*>(&g_scratch[(b + 0) * N_SAMP + j0]);
            const float4 v1 = *reinterpret_cast<const float4*>(&g_scratch[(b + 1) * N_SAMP + j0]);
            a0.x += v0.x; a0.y += v0.y; a0.z += v0.z; a0.w += v0.w;
            a1.x += v1.x; a1.y += v1.y; a1.z += v1.z; a1.w += v1.w;
        }
        const float sc = 1.0f / (float)N_OSC;
        *reinterpret_cast<float4*>(&out[j0]) = make_float4(
            (a0.x + a1.x) * sc, (a0.y + a1.y) * sc,
            (a0.z + a1.z) * sc, (a0.w + a1.w) * sc);
    }
}

extern "C" void kernel_launch(void* const* d_in, const int* in_sizes, int n_in,
                              void* d_out, int out_size) {
    const float* latent = (const float*)d_in[n_in - 1];
    for (int i = 0; i < n_in; ++i) {
        if (in_sizes[i] == 2 * HALF) { latent = (const float*)d_in[i]; break; }
    }
    float* out = (float*)d_out;

    dim3 grid(N_SAMP_BLK, N_OSC_BLK);                       // 16 x 64 = 1024 blocks
    osc_kernel<<<grid, THREADS>>>(latent, out);
}